// round 4
// baseline (speedup 1.0000x reference)
#include <cuda_runtime.h>

// Detail loss, simplified:
//   D = sum_c (infer - ref)   (per image plane)
//   out = (sum|D[w+1]-D[w-1]| + sum|D[h+1]-D[h-1]|) * 0.25 / (98*258*256)
// (zero padding; both conv means share the identical denominator since H==W,
//  and the 3 duplicated output channels cancel).

#define NIMG 98          // 2*7*7
#define IMG_H 256
#define IMG_W 256
#define ROWS 64          // rows of D per block
#define STRIPS (IMG_H / ROWS)          // 4
#define NBLOCKS (NIMG * STRIPS)        // 392  -> single wave at occ 3 on 152 SMs
#define PLANE (IMG_H * IMG_W)          // 65536
#define SMEM_BYTES ((ROWS + 2) * IMG_W * 4)   // 67584

__device__ float        g_block_sums[NBLOCKS];
__device__ unsigned int g_counter;            // zero-init; reset by last block

__global__ void __launch_bounds__(256, 3)
detail_fused(const float* __restrict__ infer, const float* __restrict__ ref,
             float* __restrict__ out) {
    extern __shared__ float Dsh[];   // (ROWS+2) x IMG_W

    const int blk   = blockIdx.x;
    const int n     = blk / STRIPS;
    const int strip = blk % STRIPS;
    const int r0    = strip * ROWS;
    const int tid   = threadIdx.x;

    const float* pi = infer + (size_t)n * 3 * PLANE;
    const float* pr = ref   + (size_t)n * 3 * PLANE;

    // ---- Load (ROWS+2) rows of D into shared; zero rows outside the image ----
    const int V4 = IMG_W / 4;  // 64 float4 per row
    #pragma unroll 1
    for (int idx = tid; idx < (ROWS + 2) * V4; idx += 256) {
        const int row = idx >> 6;          // /64
        const int c4  = idx & 63;
        const int gh  = r0 - 1 + row;
        float4 d = make_float4(0.f, 0.f, 0.f, 0.f);
        if (gh >= 0 && gh < IMG_H) {
            const size_t off = (size_t)gh * IMG_W + c4 * 4;
            #pragma unroll
            for (int c = 0; c < 3; c++) {
                const float4 a = __ldcs((const float4*)(pi + (size_t)c * PLANE + off));
                const float4 b = __ldcs((const float4*)(pr + (size_t)c * PLANE + off));
                d.x += a.x - b.x;
                d.y += a.y - b.y;
                d.z += a.z - b.z;
                d.w += a.w - b.w;
            }
        }
        *(float4*)(Dsh + row * IMG_W + c4 * 4) = d;
    }
    __syncthreads();

    // ---- Stencil walk: thread owns column w, rolls center values in regs ----
    const int w = tid;
    float sum = 0.f;
    float cm = Dsh[w];               // D[r0-1][w]
    float cc = Dsh[IMG_W + w];       // D[r0  ][w]
    #pragma unroll 8
    for (int h = 0; h < ROWS; h++) {
        const float* rowc = Dsh + (h + 1) * IMG_W;   // row r0+h
        const float* rowp = rowc + IMG_W;            // row r0+h+1
        const float cp = rowp[w];
        const float l  = (w > 0)         ? rowc[w - 1] : 0.f;
        const float r  = (w < IMG_W - 1) ? rowc[w + 1] : 0.f;
        sum += fabsf(r - l);         // horizontal gradient (0.5 folded into scale)
        sum += fabsf(cp - cm);       // vertical gradient
        cm = cc;
        cc = cp;
    }

    // ---- Block reduction ----
    #pragma unroll
    for (int off = 16; off > 0; off >>= 1)
        sum += __shfl_down_sync(0xffffffffu, sum, off);
    __shared__ float wsum[8];
    __shared__ bool  is_last;
    if ((tid & 31) == 0) wsum[tid >> 5] = sum;
    __syncthreads();
    if (tid == 0) {
        float s = 0.f;
        #pragma unroll
        for (int i = 0; i < 8; i++) s += wsum[i];
        g_block_sums[blk] = s;
        __threadfence();
        unsigned int old = atomicAdd(&g_counter, 1u);
        is_last = (old == NBLOCKS - 1);
    }
    __syncthreads();

    // ---- Last block performs the final reduction (deterministic order) ----
    if (is_last) {
        float s = 0.f;
        for (int i = tid; i < NBLOCKS; i += 256) s += g_block_sums[i];
        #pragma unroll
        for (int off = 16; off > 0; off >>= 1)
            s += __shfl_down_sync(0xffffffffu, s, off);
        if ((tid & 31) == 0) wsum[tid >> 5] = s;
        __syncthreads();
        if (tid == 0) {
            float t = 0.f;
            #pragma unroll
            for (int i = 0; i < 8; i++) t += wsum[i];
            // 0.5 (gradient coeff) * 0.5 (avg of two losses) / (98*258*256)
            out[0] = t * (0.25f / 6472704.0f);
            g_counter = 0;   // reset so every graph replay behaves identically
        }
    }
}

extern "C" void kernel_launch(void* const* d_in, const int* in_sizes, int n_in,
                              void* d_out, int out_size) {
    const float* infer = (const float*)d_in[0];
    const float* ref   = (const float*)d_in[1];
    float* out = (float*)d_out;

    cudaFuncSetAttribute(detail_fused,
                         cudaFuncAttributeMaxDynamicSharedMemorySize, SMEM_BYTES);
    detail_fused<<<NBLOCKS, 256, SMEM_BYTES>>>(infer, ref, out);
}

// round 5
// speedup vs baseline: 1.1618x; 1.1618x over previous
#include <cuda_runtime.h>

// Detail loss, simplified:
//   D = sum_c (infer - ref)   per image plane
//   out = (sum|D[w+1]-D[w-1]| + sum|D[h+1]-D[h-1]|) * 0.25 / (98*258*256)
// Warp-per-row-strip design: no shared memory, no barriers in the hot loop.
// Each lane owns 8 consecutive columns; horizontal neighbors via registers +
// two warp shuffles; vertical via a rolling 3-row register window.

#define NIMG   98            // 2*7*7
#define IMG_H  256
#define IMG_W  256
#define RSTRIP 16            // rows per warp strip
#define STRIPS (IMG_H / RSTRIP)        // 16
#define NBLK   (NIMG * STRIPS)         // 1568 one-warp blocks
#define PLANE  (IMG_H * IMG_W)

__device__ float        g_partials[NBLK];
__device__ unsigned int g_count;     // zero-init; reset each launch by last block

// Load one row of D = sum_c(infer-ref) for this lane's 8 columns (zeros if invalid).
__device__ __forceinline__ void load_row(const float* __restrict__ pi,
                                         const float* __restrict__ pr,
                                         int row, int lane, bool valid,
                                         float d[8]) {
    if (valid) {
        const size_t off = (size_t)row * IMG_W + lane * 8;
        float4 s0 = make_float4(0.f, 0.f, 0.f, 0.f);
        float4 s1 = s0;
        #pragma unroll
        for (int c = 0; c < 3; c++) {
            const float* a = pi + (size_t)c * PLANE + off;
            const float* b = pr + (size_t)c * PLANE + off;
            const float4 a0 = __ldcs((const float4*)a);
            const float4 a1 = __ldcs((const float4*)(a + 4));
            const float4 b0 = __ldcs((const float4*)b);
            const float4 b1 = __ldcs((const float4*)(b + 4));
            s0.x += a0.x - b0.x;  s0.y += a0.y - b0.y;
            s0.z += a0.z - b0.z;  s0.w += a0.w - b0.w;
            s1.x += a1.x - b1.x;  s1.y += a1.y - b1.y;
            s1.z += a1.z - b1.z;  s1.w += a1.w - b1.w;
        }
        d[0] = s0.x; d[1] = s0.y; d[2] = s0.z; d[3] = s0.w;
        d[4] = s1.x; d[5] = s1.y; d[6] = s1.z; d[7] = s1.w;
    } else {
        #pragma unroll
        for (int j = 0; j < 8; j++) d[j] = 0.f;
    }
}

__global__ void __launch_bounds__(32)
detail_kernel(const float* __restrict__ infer, const float* __restrict__ ref,
              float* __restrict__ out) {
    const int blk   = blockIdx.x;
    const int n     = blk / STRIPS;
    const int strip = blk % STRIPS;
    const int r0    = strip * RSTRIP;
    const int lane  = threadIdx.x;

    const float* pi = infer + (size_t)n * 3 * PLANE;
    const float* pr = ref   + (size_t)n * 3 * PLANE;

    float pm[8], pc[8], pn[8];
    load_row(pi, pr, r0 - 1, lane, r0 > 0, pm);
    load_row(pi, pr, r0,     lane, true,   pc);

    float sum_h = 0.f, sum_v = 0.f;

    #pragma unroll 2
    for (int h = 0; h < RSTRIP; h++) {
        const int g = r0 + h;
        load_row(pi, pr, g + 1, lane, (g + 1) < IMG_H, pn);

        // Horizontal gradient on row g (values in pc).
        float left  = __shfl_up_sync(0xffffffffu,  pc[7], 1);
        float right = __shfl_down_sync(0xffffffffu, pc[0], 1);
        if (lane == 0)  left  = 0.f;   // image edge: zero padding
        if (lane == 31) right = 0.f;
        sum_h += fabsf(pc[1] - left);
        #pragma unroll
        for (int j = 1; j < 7; j++) sum_h += fabsf(pc[j + 1] - pc[j - 1]);
        sum_h += fabsf(right - pc[6]);

        // Vertical gradient on row g.
        #pragma unroll
        for (int j = 0; j < 8; j++) sum_v += fabsf(pn[j] - pm[j]);

        // Roll the window.
        #pragma unroll
        for (int j = 0; j < 8; j++) { pm[j] = pc[j]; pc[j] = pn[j]; }
    }

    // Warp reduction.
    float s = sum_h + sum_v;
    #pragma unroll
    for (int off = 16; off > 0; off >>= 1)
        s += __shfl_down_sync(0xffffffffu, s, off);

    int last = 0;
    if (lane == 0) {
        g_partials[blk] = s;
        __threadfence();
        last = (atomicAdd(&g_count, 1u) == NBLK - 1);
    }
    last = __shfl_sync(0xffffffffu, last, 0);

    if (last) {
        float t = 0.f;
        for (int i = lane; i < NBLK; i += 32)
            t += __ldcg(&g_partials[i]);   // bypass (stale-free) L1
        #pragma unroll
        for (int off = 16; off > 0; off >>= 1)
            t += __shfl_down_sync(0xffffffffu, t, off);
        if (lane == 0) {
            // 0.5 (gradient coeff) * 0.5 (avg of two losses) / (98*258*256)
            out[0] = t * (0.25f / 6472704.0f);
            g_count = 0;   // deterministic across graph replays
        }
    }
}

extern "C" void kernel_launch(void* const* d_in, const int* in_sizes, int n_in,
                              void* d_out, int out_size) {
    const float* infer = (const float*)d_in[0];
    const float* ref   = (const float*)d_in[1];
    detail_kernel<<<NBLK, 32>>>(infer, ref, (float*)d_out);
}

// round 6
// speedup vs baseline: 1.2961x; 1.1156x over previous
#include <cuda_runtime.h>

// Detail loss, simplified:
//   D = sum_c (infer - ref)   per image plane
//   out = (sum|D[w+1]-D[w-1]| + sum|D[h+1]-D[h-1]|) * 0.25 / (98*258*256)
// Warp-per-row-strip, no smem/barriers, and a one-row-ahead software pipeline:
// raw loads for row g+2 are issued before row g+1 is combined/consumed, so each
// warp keeps ~24 LDG.128 in flight instead of 12.

#define NIMG   98            // 2*7*7
#define IMG_H  256
#define IMG_W  256
#define RSTRIP 16            // rows per warp strip
#define STRIPS (IMG_H / RSTRIP)        // 16
#define NBLK   (NIMG * STRIPS)         // 1568 one-warp blocks
#define PLANE  (IMG_H * IMG_W)

__device__ float        g_partials[NBLK];
__device__ unsigned int g_count;     // zero-init; reset each launch by last block

struct Raw {
    float4 a[6];   // infer: 3 channels x 2 float4
    float4 b[6];   // ref
};

__device__ __forceinline__ void issue_load(const float* __restrict__ pi,
                                           const float* __restrict__ pr,
                                           int row, int lane, bool valid, Raw& r) {
    if (valid) {
        const size_t off = (size_t)row * IMG_W + lane * 8;
        #pragma unroll
        for (int c = 0; c < 3; c++) {
            const float* a = pi + (size_t)c * PLANE + off;
            const float* b = pr + (size_t)c * PLANE + off;
            r.a[c * 2]     = __ldcs((const float4*)a);
            r.a[c * 2 + 1] = __ldcs((const float4*)(a + 4));
            r.b[c * 2]     = __ldcs((const float4*)b);
            r.b[c * 2 + 1] = __ldcs((const float4*)(b + 4));
        }
    } else {
        const float4 z = make_float4(0.f, 0.f, 0.f, 0.f);
        #pragma unroll
        for (int i = 0; i < 6; i++) { r.a[i] = z; r.b[i] = z; }
    }
}

__device__ __forceinline__ void combine(const Raw& r, float d[8]) {
    #pragma unroll
    for (int j = 0; j < 8; j++) d[j] = 0.f;
    #pragma unroll
    for (int c = 0; c < 3; c++) {
        const float4 a0 = r.a[c * 2], a1 = r.a[c * 2 + 1];
        const float4 b0 = r.b[c * 2], b1 = r.b[c * 2 + 1];
        d[0] += a0.x - b0.x;  d[1] += a0.y - b0.y;
        d[2] += a0.z - b0.z;  d[3] += a0.w - b0.w;
        d[4] += a1.x - b1.x;  d[5] += a1.y - b1.y;
        d[6] += a1.z - b1.z;  d[7] += a1.w - b1.w;
    }
}

__global__ void __launch_bounds__(32)
detail_kernel(const float* __restrict__ infer, const float* __restrict__ ref,
              float* __restrict__ out) {
    const int blk   = blockIdx.x;
    const int n     = blk / STRIPS;
    const int strip = blk % STRIPS;
    const int r0    = strip * RSTRIP;
    const int lane  = threadIdx.x;

    const float* pi = infer + (size_t)n * 3 * PLANE;
    const float* pr = ref   + (size_t)n * 3 * PLANE;

    // Prologue: rows r0-1, r0 (combined immediately), row r0+1 in flight.
    Raw buf[2];
    Raw rtop, rcur;
    issue_load(pi, pr, r0 - 1, lane, r0 > 0, rtop);
    issue_load(pi, pr, r0,     lane, true,   rcur);
    issue_load(pi, pr, r0 + 1, lane, true,   buf[1]);   // consumed at h=0

    float pm[8], pc[8], pn[8];
    combine(rtop, pm);
    combine(rcur, pc);

    float sum_h = 0.f, sum_v = 0.f;

    #pragma unroll 2
    for (int h = 0; h < RSTRIP; h++) {
        const int g = r0 + h;
        // Issue loads for row g+2 BEFORE consuming row g+1 (one-ahead pipeline).
        issue_load(pi, pr, g + 2, lane, (g + 2) < IMG_H && h + 1 < RSTRIP, buf[h & 1]);

        combine(buf[(h + 1) & 1], pn);   // row g+1, issued last iteration

        // Horizontal gradient on row g (values in pc).
        float left  = __shfl_up_sync(0xffffffffu,  pc[7], 1);
        float right = __shfl_down_sync(0xffffffffu, pc[0], 1);
        if (lane == 0)  left  = 0.f;
        if (lane == 31) right = 0.f;
        sum_h += fabsf(pc[1] - left);
        #pragma unroll
        for (int j = 1; j < 7; j++) sum_h += fabsf(pc[j + 1] - pc[j - 1]);
        sum_h += fabsf(right - pc[6]);

        // Vertical gradient on row g.
        #pragma unroll
        for (int j = 0; j < 8; j++) sum_v += fabsf(pn[j] - pm[j]);

        // Roll the window.
        #pragma unroll
        for (int j = 0; j < 8; j++) { pm[j] = pc[j]; pc[j] = pn[j]; }
    }

    // Warp reduction.
    float s = sum_h + sum_v;
    #pragma unroll
    for (int off = 16; off > 0; off >>= 1)
        s += __shfl_down_sync(0xffffffffu, s, off);

    int last = 0;
    if (lane == 0) {
        g_partials[blk] = s;
        __threadfence();
        last = (atomicAdd(&g_count, 1u) == NBLK - 1);
    }
    last = __shfl_sync(0xffffffffu, last, 0);

    if (last) {
        float t = 0.f;
        for (int i = lane; i < NBLK; i += 32)
            t += __ldcg(&g_partials[i]);
        #pragma unroll
        for (int off = 16; off > 0; off >>= 1)
            t += __shfl_down_sync(0xffffffffu, t, off);
        if (lane == 0) {
            // 0.5 (gradient coeff) * 0.5 (avg of two losses) / (98*258*256)
            out[0] = t * (0.25f / 6472704.0f);
            g_count = 0;   // deterministic across graph replays
        }
    }
}

extern "C" void kernel_launch(void* const* d_in, const int* in_sizes, int n_in,
                              void* d_out, int out_size) {
    const float* infer = (const float*)d_in[0];
    const float* ref   = (const float*)d_in[1];
    detail_kernel<<<NBLK, 32>>>(infer, ref, (float*)d_out);
}